// round 16
// baseline (speedup 1.0000x reference)
#include <cuda_runtime.h>
#include <cuda_fp16.h>
#include <cstdint>
#include <cstddef>

#define N_NODES 50000
#define N_EDGES 1600000
#define VOCAB   5000
#define HID     64
#define HEADS   4
#define NG      128
#define NCLS    20
#define NEG_SLOPE 0.2f

#define KPAD 5024        // 5000 padded to multiple of 32
#define NKT  157         // ceil(5000/32)

// ---------------- scratch (static device globals; no allocation) ----------------
__device__ float g_h1pre[N_NODES * HID];    // x @ W1
__device__ float g_al1s[N_NODES * HEADS];
__device__ float g_al1d[N_NODES * HEADS];
__device__ float g_h2[N_NODES * HID];       // layer2 pre-aggregation (h @ W2)
__device__ float g_al2s[N_NODES];
__device__ float g_al2d[N_NODES];
__device__ float g_pool[NG * HID];
__device__ float g_cnt[NG];
// CSR (dst-sorted edges)
__device__ int g_rowptr[N_NODES + 1];
__device__ int g_cursor[N_NODES];
__device__ int g_ssrc[N_EDGES];
// W1 in fp16, TRANSPOSED to [HID][KPAD] (k contiguous), K-tail zeroed
__device__ __align__(16) __half g_w1[HID * KPAD];

// ---------------- helpers ----------------
__device__ __forceinline__ void red_add_v2(float* p, float a, float b) {
    asm volatile("red.global.add.v2.f32 [%0], {%1, %2};" :: "l"(p), "f"(a), "f"(b) : "memory");
}
__device__ __forceinline__ void red_add_f(float* p, float v) {
    asm volatile("red.global.add.f32 [%0], %1;" :: "l"(p), "f"(v) : "memory");
}

#define MMA_F16(c, a, b0, b1)                                                   \
    asm volatile("mma.sync.aligned.m16n8k16.row.col.f32.f16.f16.f32 "           \
        "{%0,%1,%2,%3}, {%4,%5,%6,%7}, {%8,%9}, {%0,%1,%2,%3};"                 \
        : "+f"((c)[0]), "+f"((c)[1]), "+f"((c)[2]), "+f"((c)[3])                \
        : "r"((a)[0]), "r"((a)[1]), "r"((a)[2]), "r"((a)[3]), "r"(b0), "r"(b1))

__device__ __forceinline__ void ldsm_x4(uint32_t* r, uint32_t addr) {
    asm volatile("ldmatrix.sync.aligned.m8n8.x4.shared.b16 {%0,%1,%2,%3}, [%4];"
                 : "=r"(r[0]), "=r"(r[1]), "=r"(r[2]), "=r"(r[3]) : "r"(addr));
}
__device__ __forceinline__ uint32_t pack_h2(__half a, __half b) {
    __half2 t(a, b);
    return *reinterpret_cast<uint32_t*>(&t);
}

// ---------------- Kz: zero bins + pool + cnt ----------------
__global__ void k_zs() {
    int i = blockIdx.x * blockDim.x + threadIdx.x;
    if (i < N_NODES)   g_cursor[i] = 0;
    if (i < NG * HID)  g_pool[i] = 0.f;
    if (i < NG)        g_cnt[i] = 0.f;
}

// ---------------- Kh: histogram of dst ----------------
__global__ void k_hist(const int* __restrict__ dst) {
    int e = blockIdx.x * blockDim.x + threadIdx.x;
    if (e < N_EDGES) atomicAdd(&g_cursor[dst[e]], 1);
}

// ---------------- Ks: exclusive scan over bins (single block, 1024 threads) ----------------
__global__ __launch_bounds__(1024) void k_scan() {
    __shared__ int wsum[32];
    __shared__ int s_run;
    int tid = threadIdx.x, lane = tid & 31, wid = tid >> 5;
    if (tid == 0) s_run = 0;
    __syncthreads();
    for (int base = 0; base < N_NODES; base += 1024) {
        int i = base + tid;
        int v = (i < N_NODES) ? g_cursor[i] : 0;
        int x = v;
#pragma unroll
        for (int o = 1; o < 32; o <<= 1) {
            int y = __shfl_up_sync(0xffffffffu, x, o);
            if (lane >= o) x += y;
        }
        if (lane == 31) wsum[wid] = x;
        __syncthreads();
        if (wid == 0) {
            int s = wsum[lane];
#pragma unroll
            for (int o = 1; o < 32; o <<= 1) {
                int y = __shfl_up_sync(0xffffffffu, s, o);
                if (lane >= o) s += y;
            }
            wsum[lane] = s;
        }
        __syncthreads();
        int excl = x - v + (wid > 0 ? wsum[wid - 1] : 0) + s_run;
        if (i < N_NODES) { g_rowptr[i] = excl; g_cursor[i] = excl; }
        __syncthreads();
        if (tid == 0) s_run += wsum[31];
        __syncthreads();
    }
    if (tid == 0) g_rowptr[N_NODES] = s_run;
}

// ---------------- Kc: scatter edges into dst-sorted order ----------------
__global__ void k_scatter(const int* __restrict__ src, const int* __restrict__ dst) {
    int e = blockIdx.x * blockDim.x + threadIdx.x;
    if (e < N_EDGES) {
        int p = atomicAdd(&g_cursor[dst[e]], 1);
        g_ssrc[p] = src[e];
    }
}

// ---------------- K0b: convert + transpose W1 -> g_w1 [HID][KPAD] fp16 ----------------
__global__ void k_prepW(const float* __restrict__ W1) {
    int i = blockIdx.x * blockDim.x + threadIdx.x;
    if (i >= HID * KPAD) return;
    int n = i / KPAD, k = i - n * KPAD;
    float v = (k < VOCAB) ? W1[(size_t)k * HID + n] : 0.f;
    g_w1[i] = __float2half_rn(v);
}

// ---------------- K1: GEMM1 via fp16 tensor-core MMA (pure fp16, fp32 acc) ----------------
// h1[50000,64] = x @ W1. Double-buffered smem, one __syncthreads per K-iter.
// __launch_bounds__(256,3): cap regs at 84 -> 3 CTAs/SM -> 444 concurrent >= 391 tiles
// (single wave; kills the 95-CTA tail wave). Epilogue fuses layer-1 attention logits.
#define AROW 40

__global__ __launch_bounds__(256, 3) void k_gemm1_mma(const float* __restrict__ A,
                                                      const float* __restrict__ a_src1,
                                                      const float* __restrict__ a_dst1) {
    __shared__ __align__(16) __half as[2][128 * AROW];
    __shared__ __align__(16) __half bs[2][64 * AROW];
    __shared__ float s_as[HID], s_ad[HID];

    const int tid  = threadIdx.x;
    const int lane = tid & 31;
    const int w    = tid >> 5;
    const int m0   = blockIdx.x * 128;

    if (tid < HID) { s_as[tid] = a_src1[tid]; s_ad[tid] = a_dst1[tid]; }

    float acc[8][4];
#pragma unroll
    for (int nt = 0; nt < 8; ++nt)
#pragma unroll
        for (int j = 0; j < 4; ++j) acc[nt][j] = 0.f;

    float4 areg[4];
    uint4 b_reg;

    const int a_row = tid >> 3;
    const int a_cq  = tid & 7;
    const int b_n   = tid >> 2;
    const int b_kq  = tid & 3;

    auto ldAB = [&](int kt) {
#pragma unroll
        for (int i = 0; i < 4; ++i) {
            int row = a_row + i * 32;
            int gr = m0 + row;
            int gk = kt + a_cq * 4;
            float4 v = make_float4(0.f, 0.f, 0.f, 0.f);
            if (gr < N_NODES && gk < VOCAB)
                v = *reinterpret_cast<const float4*>(&A[(size_t)gr * VOCAB + gk]);
            areg[i] = v;
        }
        b_reg = *reinterpret_cast<const uint4*>(&g_w1[b_n * KPAD + kt + b_kq * 8]);
    };

    auto stAB = [&](int buf) {
#pragma unroll
        for (int i = 0; i < 4; ++i) {
            int row = a_row + i * 32;
            float4 v = areg[i];
            *reinterpret_cast<uint2*>(&as[buf][row * AROW + a_cq * 4]) =
                make_uint2(pack_h2(__float2half_rn(v.x), __float2half_rn(v.y)),
                           pack_h2(__float2half_rn(v.z), __float2half_rn(v.w)));
        }
        *reinterpret_cast<uint4*>(&bs[buf][b_n * AROW + b_kq * 8]) = b_reg;
    };

    const uint32_t as_u0 = (uint32_t)__cvta_generic_to_shared(&as[0][0]);
    const uint32_t as_u1 = (uint32_t)__cvta_generic_to_shared(&as[1][0]);
    const uint32_t a_frag_off = (uint32_t)((w * 16 + (lane & 15)) * AROW * 2 + (lane >> 4) * 16);
    const int bn = lane >> 2;
    const int bk = (lane & 3) * 2;

    ldAB(0);
    stAB(0);
    __syncthreads();

    for (int it = 0; it < NKT; ++it) {
        const int buf = it & 1;
        if (it + 1 < NKT) ldAB((it + 1) * 32);

        const uint32_t as_u = buf ? as_u1 : as_u0;
        const __half* bsb = &bs[buf][0];
#pragma unroll
        for (int ks = 0; ks < 32; ks += 16) {
            uint32_t ah[4];
            ldsm_x4(ah, as_u + a_frag_off + ks * 2);
#pragma unroll
            for (int nt = 0; nt < 8; ++nt) {
                const __half* bp = &bsb[(nt * 8 + bn) * AROW + ks + bk];
                uint32_t b0 = *reinterpret_cast<const uint32_t*>(bp);
                uint32_t b1 = *reinterpret_cast<const uint32_t*>(bp + 8);
                MMA_F16(acc[nt], ah, b0, b1);
            }
        }
        if (it + 1 < NKT) stAB(buf ^ 1);
        __syncthreads();
    }

    const int r0 = m0 + w * 16 + (lane >> 2);
    const int c0 = 2 * (lane & 3);
#pragma unroll
    for (int nt = 0; nt < 8; ++nt) {
        int col = nt * 8 + c0;
        if (r0 < N_NODES)
            *reinterpret_cast<float2*>(&g_h1pre[(size_t)r0 * HID + col]) =
                make_float2(acc[nt][0], acc[nt][1]);
        if (r0 + 8 < N_NODES)
            *reinterpret_cast<float2*>(&g_h1pre[(size_t)(r0 + 8) * HID + col]) =
                make_float2(acc[nt][2], acc[nt][3]);
    }

    // fused attention logits
    float ps[HEADS][2], pd[HEADS][2];
#pragma unroll
    for (int p = 0; p < HEADS; ++p) {
#pragma unroll
        for (int rr = 0; rr < 2; ++rr) {
            float s = 0.f, d = 0.f;
#pragma unroll
            for (int ntl = 0; ntl < 2; ++ntl) {
                int nt = 2 * p + ntl;
#pragma unroll
                for (int cc = 0; cc < 2; ++cc) {
                    int col = nt * 8 + c0 + cc;
                    float v = acc[nt][rr * 2 + cc];
                    s += v * s_as[col];
                    d += v * s_ad[col];
                }
            }
            ps[p][rr] = s; pd[p][rr] = d;
        }
    }
#pragma unroll
    for (int off = 1; off <= 2; off <<= 1) {
#pragma unroll
        for (int p = 0; p < HEADS; ++p) {
#pragma unroll
            for (int rr = 0; rr < 2; ++rr) {
                ps[p][rr] += __shfl_xor_sync(0xffffffffu, ps[p][rr], off);
                pd[p][rr] += __shfl_xor_sync(0xffffffffu, pd[p][rr], off);
            }
        }
    }
    const int q = lane & 3;
    if (r0 < N_NODES) {
        g_al1s[r0 * HEADS + q] = ps[q][0];
        g_al1d[r0 * HEADS + q] = pd[q][0];
    }
    if (r0 + 8 < N_NODES) {
        g_al1s[(r0 + 8) * HEADS + q] = ps[q][1];
        g_al1d[(r0 + 8) * HEADS + q] = pd[q][1];
    }
}

// ---------------- K3: edge pass layer 1 (CSR warp-per-node) + fused fin1 + GEMM2 + logits2 ----
// After aggregating node n's post-ELU row h[n] (2 cols/lane), do the row-local
// GEMM2 h2[n] = h[n] @ W2 via shfl-broadcast against W2 staged in smem, plus the
// layer-2 attention logits. Replaces the separate k_layer2_mm kernel and g_h.
__global__ __launch_bounds__(256) void k_edge1_fused(const float* __restrict__ b1,
                                                     const float* __restrict__ W2,
                                                     const float* __restrict__ as2,
                                                     const float* __restrict__ ad2) {
    __shared__ float s_b1[HID];
    __shared__ float s_W2[HID * HID];     // [k][c] row-major, 16 KB
    __shared__ float s_as2[HID], s_ad2[HID];
    for (int i = threadIdx.x; i < HID * HID; i += 256) s_W2[i] = W2[i];
    if (threadIdx.x < HID) {
        s_b1[threadIdx.x]  = b1[threadIdx.x];
        s_as2[threadIdx.x] = as2[threadIdx.x];
        s_ad2[threadIdx.x] = ad2[threadIdx.x];
    }
    __syncthreads();

    const int lane = threadIdx.x & 31;
    const int wid  = threadIdx.x >> 5;
    const int c0   = 2 * lane;
    const int head = lane >> 3;

    for (int n = blockIdx.x * 8 + wid; n < N_NODES; n += gridDim.x * 8) {
        float aldn = g_al1d[n * HEADS + head];
        // self loop
        float al = g_al1s[n * HEADS + head] + aldn;
        float ee = al > 0.f ? al : NEG_SLOPE * al;
        float wgt = __expf(ee);
        float2 hv = *reinterpret_cast<const float2*>(&g_h1pre[(size_t)n * HID + c0]);
        float ax = wgt * hv.x, ay = wgt * hv.y, den = wgt;

        int beg = g_rowptr[n], end = g_rowptr[n + 1];
        for (int base = beg; base < end; base += 32) {
            int rem = end - base;
            int j = base + lane;
            int s = (lane < rem) ? g_ssrc[j] : 0;
            if (rem >= 32) {
#pragma unroll 8
                for (int t = 0; t < 32; ++t) {
                    int sj = __shfl_sync(0xffffffffu, s, t);
                    float a2 = g_al1s[sj * HEADS + head] + aldn;
                    float e2 = a2 > 0.f ? a2 : NEG_SLOPE * a2;
                    float w2 = __expf(e2);
                    float2 h2 = *reinterpret_cast<const float2*>(&g_h1pre[(size_t)sj * HID + c0]);
                    ax += w2 * h2.x; ay += w2 * h2.y; den += w2;
                }
            } else {
                for (int t = 0; t < rem; ++t) {
                    int sj = __shfl_sync(0xffffffffu, s, t);
                    float a2 = g_al1s[sj * HEADS + head] + aldn;
                    float e2 = a2 > 0.f ? a2 : NEG_SLOPE * a2;
                    float w2 = __expf(e2);
                    float2 h2 = *reinterpret_cast<const float2*>(&g_h1pre[(size_t)sj * HID + c0]);
                    ax += w2 * h2.x; ay += w2 * h2.y; den += w2;
                }
            }
        }
        float inv = 1.f / (den + 1e-16f);
        float vx = ax * inv + s_b1[c0];
        float vy = ay * inv + s_b1[c0 + 1];
        vx = vx > 0.f ? vx : expm1f(vx);      // h[n][c0], h[n][c0+1] post-ELU
        vy = vy > 0.f ? vy : expm1f(vy);

        // fused GEMM2: h2[c] = sum_k h[k] * W2[k][c]; lane holds cols c0, c0+1
        float h2a = 0.f, h2b = 0.f;
#pragma unroll 8
        for (int t = 0; t < 32; ++t) {
            float hx = __shfl_sync(0xffffffffu, vx, t);   // h[2t]
            float hy = __shfl_sync(0xffffffffu, vy, t);   // h[2t+1]
            float2 w0 = *reinterpret_cast<const float2*>(&s_W2[(2 * t) * HID + c0]);
            float2 w1 = *reinterpret_cast<const float2*>(&s_W2[(2 * t + 1) * HID + c0]);
            h2a += hx * w0.x + hy * w1.x;
            h2b += hx * w0.y + hy * w1.y;
        }
        *reinterpret_cast<float2*>(&g_h2[(size_t)n * HID + c0]) = make_float2(h2a, h2b);

        // layer-2 logits
        float vs = h2a * s_as2[c0] + h2b * s_as2[c0 + 1];
        float vd = h2a * s_ad2[c0] + h2b * s_ad2[c0 + 1];
#pragma unroll
        for (int off = 16; off > 0; off >>= 1) {
            vs += __shfl_xor_sync(0xffffffffu, vs, off);
            vd += __shfl_xor_sync(0xffffffffu, vd, off);
        }
        if (lane == 0) { g_al2s[n] = vs; g_al2d[n] = vd; }
    }
}

// ---------------- K6: edge pass layer 2, CSR warp-per-node, fused fin2 + pool ----------------
__global__ __launch_bounds__(256) void k_edge2_csr(const float* __restrict__ b2,
                                                   const int* __restrict__ batch) {
    __shared__ float s_b2[HID];
    if (threadIdx.x < HID) s_b2[threadIdx.x] = b2[threadIdx.x];
    __syncthreads();

    int n = blockIdx.x * 8 + (threadIdx.x >> 5);
    if (n >= N_NODES) return;
    int lane = threadIdx.x & 31;
    int c0 = 2 * lane;

    float aldn = g_al2d[n];
    float al = g_al2s[n] + aldn;
    float ee = al > 0.f ? al : NEG_SLOPE * al;
    float wgt = __expf(ee);
    float2 hv = *reinterpret_cast<const float2*>(&g_h2[(size_t)n * HID + c0]);
    float ax = wgt * hv.x, ay = wgt * hv.y, den = wgt;

    int beg = g_rowptr[n], end = g_rowptr[n + 1];
    for (int base = beg; base < end; base += 32) {
        int rem = end - base;
        int j = base + lane;
        int s = (lane < rem) ? g_ssrc[j] : 0;
        if (rem >= 32) {
#pragma unroll 8
            for (int t = 0; t < 32; ++t) {
                int sj = __shfl_sync(0xffffffffu, s, t);
                float a2 = g_al2s[sj] + aldn;
                float e2 = a2 > 0.f ? a2 : NEG_SLOPE * a2;
                float w2 = __expf(e2);
                float2 h2 = *reinterpret_cast<const float2*>(&g_h2[(size_t)sj * HID + c0]);
                ax += w2 * h2.x; ay += w2 * h2.y; den += w2;
            }
        } else {
            for (int t = 0; t < rem; ++t) {
                int sj = __shfl_sync(0xffffffffu, s, t);
                float a2 = g_al2s[sj] + aldn;
                float e2 = a2 > 0.f ? a2 : NEG_SLOPE * a2;
                float w2 = __expf(e2);
                float2 h2 = *reinterpret_cast<const float2*>(&g_h2[(size_t)sj * HID + c0]);
                ax += w2 * h2.x; ay += w2 * h2.y; den += w2;
            }
        }
    }
    float inv = 1.f / (den + 1e-16f);
    float vx = ax * inv + s_b2[c0];
    float vy = ay * inv + s_b2[c0 + 1];
    vx = vx > 0.f ? vx : expm1f(vx);
    vy = vy > 0.f ? vy : expm1f(vy);
    int b = batch[n];
    red_add_v2(&g_pool[b * HID + c0], vx, vy);
    if (lane == 0) red_add_f(&g_cnt[b], 1.f);
}

// ---------------- K8: classifier + log_softmax ----------------
__global__ void k_cls(const float* __restrict__ Wc, const float* __restrict__ bc,
                      float* __restrict__ out) {
    __shared__ float Ws[HID * NCLS];
    __shared__ float bs[NCLS];
    for (int i = threadIdx.x; i < HID * NCLS; i += blockDim.x) Ws[i] = Wc[i];
    if (threadIdx.x < NCLS) bs[threadIdx.x] = bc[threadIdx.x];
    __syncthreads();
    int g = threadIdx.x;
    if (g >= NG) return;
    float inv = 1.f / fmaxf(g_cnt[g], 1.f);
    float logit[NCLS];
#pragma unroll
    for (int q = 0; q < NCLS; ++q) logit[q] = bs[q];
    for (int c = 0; c < HID; ++c) {
        float pv = g_pool[g * HID + c] * inv;
#pragma unroll
        for (int q = 0; q < NCLS; ++q) logit[q] += pv * Ws[c * NCLS + q];
    }
    float m = logit[0];
#pragma unroll
    for (int q = 1; q < NCLS; ++q) m = fmaxf(m, logit[q]);
    float ssum = 0.f;
#pragma unroll
    for (int q = 0; q < NCLS; ++q) ssum += expf(logit[q] - m);
    float lse = m + logf(ssum);
#pragma unroll
    for (int q = 0; q < NCLS; ++q) out[g * NCLS + q] = logit[q] - lse;
}

// ---------------- launcher ----------------
extern "C" void kernel_launch(void* const* d_in, const int* in_sizes, int n_in,
                              void* d_out, int out_size) {
    const float* x      = (const float*)d_in[0];
    const int*   ei     = (const int*)  d_in[1];
    const int*   batch  = (const int*)  d_in[2];
    const float* W1     = (const float*)d_in[3];
    const float* a_src1 = (const float*)d_in[4];
    const float* a_dst1 = (const float*)d_in[5];
    const float* b1     = (const float*)d_in[6];
    const float* W2     = (const float*)d_in[7];
    const float* a_src2 = (const float*)d_in[8];
    const float* a_dst2 = (const float*)d_in[9];
    const float* b2     = (const float*)d_in[10];
    const float* Wc     = (const float*)d_in[11];
    const float* bc     = (const float*)d_in[12];
    float* out = (float*)d_out;
    const int* srcp = ei;
    const int* dstp = ei + N_EDGES;

    static cudaStream_t s_side = nullptr;
    static cudaEvent_t  s_fork = nullptr, s_join = nullptr;
    if (s_side == nullptr) {
        cudaStreamCreateWithFlags(&s_side, cudaStreamNonBlocking);
        cudaEventCreateWithFlags(&s_fork, cudaEventDisableTiming);
        cudaEventCreateWithFlags(&s_join, cudaEventDisableTiming);
    }

    // fork: CSR build on side stream, GEMM path on main stream (independent dataflows)
    cudaEventRecord(s_fork, 0);
    cudaStreamWaitEvent(s_side, s_fork, 0);

    k_zs<<<(N_NODES + 255) / 256, 256, 0, s_side>>>();
    k_hist<<<(N_EDGES + 255) / 256, 256, 0, s_side>>>(dstp);
    k_scan<<<1, 1024, 0, s_side>>>();
    k_scatter<<<(N_EDGES + 255) / 256, 256, 0, s_side>>>(srcp, dstp);
    cudaEventRecord(s_join, s_side);

    k_prepW<<<(HID * KPAD + 255) / 256, 256>>>(W1);
    k_gemm1_mma<<<(N_NODES + 127) / 128, 256>>>(x, a_src1, a_dst1);

    // join: edge pass needs both GEMM output and CSR
    cudaStreamWaitEvent(0, s_join, 0);

    k_edge1_fused<<<1480, 256>>>(b1, W2, a_src2, a_dst2);
    k_edge2_csr<<<(N_NODES + 7) / 8, 256>>>(b2, batch);
    k_cls<<<1, 128>>>(Wc, bc, out);
}

// round 17
// speedup vs baseline: 1.0160x; 1.0160x over previous
#include <cuda_runtime.h>
#include <cuda_fp16.h>
#include <cstdint>
#include <cstddef>

#define N_NODES 50000
#define N_EDGES 1600000
#define VOCAB   5000
#define HID     64
#define HEADS   4
#define NG      128
#define NCLS    20
#define NEG_SLOPE 0.2f

#define KPAD 5024        // 5000 padded to multiple of 32
#define NKT  157         // ceil(5000/32)

// ---------------- scratch (static device globals; no allocation) ----------------
__device__ float g_h1pre[N_NODES * HID];    // x @ W1
__device__ float g_al1s[N_NODES * HEADS];
__device__ float g_al1d[N_NODES * HEADS];
__device__ float g_h2[N_NODES * HID];       // layer2 pre-aggregation (h @ W2)
__device__ float g_al2s[N_NODES];
__device__ float g_al2d[N_NODES];
__device__ float g_pool[NG * HID];
__device__ float g_cnt[NG];
// CSR (dst-sorted edges)
__device__ int g_rowptr[N_NODES + 1];
__device__ int g_cursor[N_NODES];
__device__ int g_ssrc[N_EDGES];
// W1 in fp16, TRANSPOSED to [HID][KPAD] (k contiguous), K-tail zeroed
__device__ __align__(16) __half g_w1[HID * KPAD];

// ---------------- helpers ----------------
__device__ __forceinline__ void red_add_v2(float* p, float a, float b) {
    asm volatile("red.global.add.v2.f32 [%0], {%1, %2};" :: "l"(p), "f"(a), "f"(b) : "memory");
}
__device__ __forceinline__ void red_add_f(float* p, float v) {
    asm volatile("red.global.add.f32 [%0], %1;" :: "l"(p), "f"(v) : "memory");
}

#define MMA_F16(c, a, b0, b1)                                                   \
    asm volatile("mma.sync.aligned.m16n8k16.row.col.f32.f16.f16.f32 "           \
        "{%0,%1,%2,%3}, {%4,%5,%6,%7}, {%8,%9}, {%0,%1,%2,%3};"                 \
        : "+f"((c)[0]), "+f"((c)[1]), "+f"((c)[2]), "+f"((c)[3])                \
        : "r"((a)[0]), "r"((a)[1]), "r"((a)[2]), "r"((a)[3]), "r"(b0), "r"(b1))

__device__ __forceinline__ void ldsm_x4(uint32_t* r, uint32_t addr) {
    asm volatile("ldmatrix.sync.aligned.m8n8.x4.shared.b16 {%0,%1,%2,%3}, [%4];"
                 : "=r"(r[0]), "=r"(r[1]), "=r"(r[2]), "=r"(r[3]) : "r"(addr));
}
__device__ __forceinline__ uint32_t pack_h2(__half a, __half b) {
    __half2 t(a, b);
    return *reinterpret_cast<uint32_t*>(&t);
}

// ---------------- Kz: zero bins + pool + cnt ----------------
__global__ void k_zs() {
    int i = blockIdx.x * blockDim.x + threadIdx.x;
    if (i < N_NODES)   g_cursor[i] = 0;
    if (i < NG * HID)  g_pool[i] = 0.f;
    if (i < NG)        g_cnt[i] = 0.f;
}

// ---------------- Kh: histogram of dst ----------------
__global__ void k_hist(const int* __restrict__ dst) {
    int e = blockIdx.x * blockDim.x + threadIdx.x;
    if (e < N_EDGES) atomicAdd(&g_cursor[dst[e]], 1);
}

// ---------------- Ks: exclusive scan over bins (single block, 1024 threads) ----------------
__global__ __launch_bounds__(1024) void k_scan() {
    __shared__ int wsum[32];
    __shared__ int s_run;
    int tid = threadIdx.x, lane = tid & 31, wid = tid >> 5;
    if (tid == 0) s_run = 0;
    __syncthreads();
    for (int base = 0; base < N_NODES; base += 1024) {
        int i = base + tid;
        int v = (i < N_NODES) ? g_cursor[i] : 0;
        int x = v;
#pragma unroll
        for (int o = 1; o < 32; o <<= 1) {
            int y = __shfl_up_sync(0xffffffffu, x, o);
            if (lane >= o) x += y;
        }
        if (lane == 31) wsum[wid] = x;
        __syncthreads();
        if (wid == 0) {
            int s = wsum[lane];
#pragma unroll
            for (int o = 1; o < 32; o <<= 1) {
                int y = __shfl_up_sync(0xffffffffu, s, o);
                if (lane >= o) s += y;
            }
            wsum[lane] = s;
        }
        __syncthreads();
        int excl = x - v + (wid > 0 ? wsum[wid - 1] : 0) + s_run;
        if (i < N_NODES) { g_rowptr[i] = excl; g_cursor[i] = excl; }
        __syncthreads();
        if (tid == 0) s_run += wsum[31];
        __syncthreads();
    }
    if (tid == 0) g_rowptr[N_NODES] = s_run;
}

// ---------------- Kc: scatter edges into dst-sorted order ----------------
__global__ void k_scatter(const int* __restrict__ src, const int* __restrict__ dst) {
    int e = blockIdx.x * blockDim.x + threadIdx.x;
    if (e < N_EDGES) {
        int p = atomicAdd(&g_cursor[dst[e]], 1);
        g_ssrc[p] = src[e];
    }
}

// ---------------- K0b: convert + transpose W1 -> g_w1 [HID][KPAD] fp16 ----------------
__global__ void k_prepW(const float* __restrict__ W1) {
    int i = blockIdx.x * blockDim.x + threadIdx.x;
    if (i >= HID * KPAD) return;
    int n = i / KPAD, k = i - n * KPAD;
    float v = (k < VOCAB) ? W1[(size_t)k * HID + n] : 0.f;
    g_w1[i] = __float2half_rn(v);
}

// ---------------- K1: GEMM1 via fp16 tensor-core MMA (pure fp16, fp32 acc) ----------------
// h1[50000,64] = x @ W1. Double-buffered smem, one __syncthreads per K-iter.
// No min-blocks cap: the (256,3) 84-reg cap forced spills in stAB (R16 regression).
// Epilogue fuses the layer-1 attention logit dot products.
#define AROW 40

__global__ __launch_bounds__(256) void k_gemm1_mma(const float* __restrict__ A,
                                                   const float* __restrict__ a_src1,
                                                   const float* __restrict__ a_dst1) {
    __shared__ __align__(16) __half as[2][128 * AROW];
    __shared__ __align__(16) __half bs[2][64 * AROW];
    __shared__ float s_as[HID], s_ad[HID];

    const int tid  = threadIdx.x;
    const int lane = tid & 31;
    const int w    = tid >> 5;
    const int m0   = blockIdx.x * 128;

    if (tid < HID) { s_as[tid] = a_src1[tid]; s_ad[tid] = a_dst1[tid]; }

    float acc[8][4];
#pragma unroll
    for (int nt = 0; nt < 8; ++nt)
#pragma unroll
        for (int j = 0; j < 4; ++j) acc[nt][j] = 0.f;

    float4 areg[4];
    uint4 b_reg;

    const int a_row = tid >> 3;
    const int a_cq  = tid & 7;
    const int b_n   = tid >> 2;
    const int b_kq  = tid & 3;

    auto ldAB = [&](int kt) {
#pragma unroll
        for (int i = 0; i < 4; ++i) {
            int row = a_row + i * 32;
            int gr = m0 + row;
            int gk = kt + a_cq * 4;
            float4 v = make_float4(0.f, 0.f, 0.f, 0.f);
            if (gr < N_NODES && gk < VOCAB)
                v = *reinterpret_cast<const float4*>(&A[(size_t)gr * VOCAB + gk]);
            areg[i] = v;
        }
        b_reg = *reinterpret_cast<const uint4*>(&g_w1[b_n * KPAD + kt + b_kq * 8]);
    };

    auto stAB = [&](int buf) {
#pragma unroll
        for (int i = 0; i < 4; ++i) {
            int row = a_row + i * 32;
            float4 v = areg[i];
            *reinterpret_cast<uint2*>(&as[buf][row * AROW + a_cq * 4]) =
                make_uint2(pack_h2(__float2half_rn(v.x), __float2half_rn(v.y)),
                           pack_h2(__float2half_rn(v.z), __float2half_rn(v.w)));
        }
        *reinterpret_cast<uint4*>(&bs[buf][b_n * AROW + b_kq * 8]) = b_reg;
    };

    const uint32_t as_u0 = (uint32_t)__cvta_generic_to_shared(&as[0][0]);
    const uint32_t as_u1 = (uint32_t)__cvta_generic_to_shared(&as[1][0]);
    const uint32_t a_frag_off = (uint32_t)((w * 16 + (lane & 15)) * AROW * 2 + (lane >> 4) * 16);
    const int bn = lane >> 2;
    const int bk = (lane & 3) * 2;

    ldAB(0);
    stAB(0);
    __syncthreads();

    for (int it = 0; it < NKT; ++it) {
        const int buf = it & 1;
        if (it + 1 < NKT) ldAB((it + 1) * 32);

        const uint32_t as_u = buf ? as_u1 : as_u0;
        const __half* bsb = &bs[buf][0];
#pragma unroll
        for (int ks = 0; ks < 32; ks += 16) {
            uint32_t ah[4];
            ldsm_x4(ah, as_u + a_frag_off + ks * 2);
#pragma unroll
            for (int nt = 0; nt < 8; ++nt) {
                const __half* bp = &bsb[(nt * 8 + bn) * AROW + ks + bk];
                uint32_t b0 = *reinterpret_cast<const uint32_t*>(bp);
                uint32_t b1 = *reinterpret_cast<const uint32_t*>(bp + 8);
                MMA_F16(acc[nt], ah, b0, b1);
            }
        }
        if (it + 1 < NKT) stAB(buf ^ 1);
        __syncthreads();
    }

    const int r0 = m0 + w * 16 + (lane >> 2);
    const int c0 = 2 * (lane & 3);
#pragma unroll
    for (int nt = 0; nt < 8; ++nt) {
        int col = nt * 8 + c0;
        if (r0 < N_NODES)
            *reinterpret_cast<float2*>(&g_h1pre[(size_t)r0 * HID + col]) =
                make_float2(acc[nt][0], acc[nt][1]);
        if (r0 + 8 < N_NODES)
            *reinterpret_cast<float2*>(&g_h1pre[(size_t)(r0 + 8) * HID + col]) =
                make_float2(acc[nt][2], acc[nt][3]);
    }

    // fused attention logits
    float ps[HEADS][2], pd[HEADS][2];
#pragma unroll
    for (int p = 0; p < HEADS; ++p) {
#pragma unroll
        for (int rr = 0; rr < 2; ++rr) {
            float s = 0.f, d = 0.f;
#pragma unroll
            for (int ntl = 0; ntl < 2; ++ntl) {
                int nt = 2 * p + ntl;
#pragma unroll
                for (int cc = 0; cc < 2; ++cc) {
                    int col = nt * 8 + c0 + cc;
                    float v = acc[nt][rr * 2 + cc];
                    s += v * s_as[col];
                    d += v * s_ad[col];
                }
            }
            ps[p][rr] = s; pd[p][rr] = d;
        }
    }
#pragma unroll
    for (int off = 1; off <= 2; off <<= 1) {
#pragma unroll
        for (int p = 0; p < HEADS; ++p) {
#pragma unroll
            for (int rr = 0; rr < 2; ++rr) {
                ps[p][rr] += __shfl_xor_sync(0xffffffffu, ps[p][rr], off);
                pd[p][rr] += __shfl_xor_sync(0xffffffffu, pd[p][rr], off);
            }
        }
    }
    const int q = lane & 3;
    if (r0 < N_NODES) {
        g_al1s[r0 * HEADS + q] = ps[q][0];
        g_al1d[r0 * HEADS + q] = pd[q][0];
    }
    if (r0 + 8 < N_NODES) {
        g_al1s[(r0 + 8) * HEADS + q] = ps[q][1];
        g_al1d[(r0 + 8) * HEADS + q] = pd[q][1];
    }
}

// ---------------- K3: edge pass layer 1 (CSR warp-per-node) + fused fin1 + GEMM2 + logits2 ----
__global__ __launch_bounds__(256) void k_edge1_fused(const float* __restrict__ b1,
                                                     const float* __restrict__ W2,
                                                     const float* __restrict__ as2,
                                                     const float* __restrict__ ad2) {
    __shared__ float s_b1[HID];
    __shared__ float s_W2[HID * HID];     // [k][c] row-major, 16 KB
    __shared__ float s_as2[HID], s_ad2[HID];
    for (int i = threadIdx.x; i < HID * HID; i += 256) s_W2[i] = W2[i];
    if (threadIdx.x < HID) {
        s_b1[threadIdx.x]  = b1[threadIdx.x];
        s_as2[threadIdx.x] = as2[threadIdx.x];
        s_ad2[threadIdx.x] = ad2[threadIdx.x];
    }
    __syncthreads();

    const int lane = threadIdx.x & 31;
    const int wid  = threadIdx.x >> 5;
    const int c0   = 2 * lane;
    const int head = lane >> 3;

    for (int n = blockIdx.x * 8 + wid; n < N_NODES; n += gridDim.x * 8) {
        float aldn = g_al1d[n * HEADS + head];
        // self loop
        float al = g_al1s[n * HEADS + head] + aldn;
        float ee = al > 0.f ? al : NEG_SLOPE * al;
        float wgt = __expf(ee);
        float2 hv = *reinterpret_cast<const float2*>(&g_h1pre[(size_t)n * HID + c0]);
        float ax = wgt * hv.x, ay = wgt * hv.y, den = wgt;

        int beg = g_rowptr[n], end = g_rowptr[n + 1];
        for (int base = beg; base < end; base += 32) {
            int rem = end - base;
            int j = base + lane;
            int s = (lane < rem) ? g_ssrc[j] : 0;
            if (rem >= 32) {
#pragma unroll 8
                for (int t = 0; t < 32; ++t) {
                    int sj = __shfl_sync(0xffffffffu, s, t);
                    float a2 = g_al1s[sj * HEADS + head] + aldn;
                    float e2 = a2 > 0.f ? a2 : NEG_SLOPE * a2;
                    float w2 = __expf(e2);
                    float2 h2 = *reinterpret_cast<const float2*>(&g_h1pre[(size_t)sj * HID + c0]);
                    ax += w2 * h2.x; ay += w2 * h2.y; den += w2;
                }
            } else {
                for (int t = 0; t < rem; ++t) {
                    int sj = __shfl_sync(0xffffffffu, s, t);
                    float a2 = g_al1s[sj * HEADS + head] + aldn;
                    float e2 = a2 > 0.f ? a2 : NEG_SLOPE * a2;
                    float w2 = __expf(e2);
                    float2 h2 = *reinterpret_cast<const float2*>(&g_h1pre[(size_t)sj * HID + c0]);
                    ax += w2 * h2.x; ay += w2 * h2.y; den += w2;
                }
            }
        }
        float inv = 1.f / (den + 1e-16f);
        float vx = ax * inv + s_b1[c0];
        float vy = ay * inv + s_b1[c0 + 1];
        vx = vx > 0.f ? vx : expm1f(vx);      // h[n][c0], h[n][c0+1] post-ELU
        vy = vy > 0.f ? vy : expm1f(vy);

        // fused GEMM2: h2[c] = sum_k h[k] * W2[k][c]; lane holds cols c0, c0+1
        float h2a = 0.f, h2b = 0.f;
#pragma unroll 8
        for (int t = 0; t < 32; ++t) {
            float hx = __shfl_sync(0xffffffffu, vx, t);   // h[2t]
            float hy = __shfl_sync(0xffffffffu, vy, t);   // h[2t+1]
            float2 w0 = *reinterpret_cast<const float2*>(&s_W2[(2 * t) * HID + c0]);
            float2 w1 = *reinterpret_cast<const float2*>(&s_W2[(2 * t + 1) * HID + c0]);
            h2a += hx * w0.x + hy * w1.x;
            h2b += hx * w0.y + hy * w1.y;
        }
        *reinterpret_cast<float2*>(&g_h2[(size_t)n * HID + c0]) = make_float2(h2a, h2b);

        // layer-2 logits
        float vs = h2a * s_as2[c0] + h2b * s_as2[c0 + 1];
        float vd = h2a * s_ad2[c0] + h2b * s_ad2[c0 + 1];
#pragma unroll
        for (int off = 16; off > 0; off >>= 1) {
            vs += __shfl_xor_sync(0xffffffffu, vs, off);
            vd += __shfl_xor_sync(0xffffffffu, vd, off);
        }
        if (lane == 0) { g_al2s[n] = vs; g_al2d[n] = vd; }
    }
}

// ---------------- K6: edge pass layer 2, CSR warp-per-node, fused fin2 + pool ----------------
__global__ __launch_bounds__(256) void k_edge2_csr(const float* __restrict__ b2,
                                                   const int* __restrict__ batch) {
    __shared__ float s_b2[HID];
    if (threadIdx.x < HID) s_b2[threadIdx.x] = b2[threadIdx.x];
    __syncthreads();

    int n = blockIdx.x * 8 + (threadIdx.x >> 5);
    if (n >= N_NODES) return;
    int lane = threadIdx.x & 31;
    int c0 = 2 * lane;

    float aldn = g_al2d[n];
    float al = g_al2s[n] + aldn;
    float ee = al > 0.f ? al : NEG_SLOPE * al;
    float wgt = __expf(ee);
    float2 hv = *reinterpret_cast<const float2*>(&g_h2[(size_t)n * HID + c0]);
    float ax = wgt * hv.x, ay = wgt * hv.y, den = wgt;

    int beg = g_rowptr[n], end = g_rowptr[n + 1];
    for (int base = beg; base < end; base += 32) {
        int rem = end - base;
        int j = base + lane;
        int s = (lane < rem) ? g_ssrc[j] : 0;
        if (rem >= 32) {
#pragma unroll 8
            for (int t = 0; t < 32; ++t) {
                int sj = __shfl_sync(0xffffffffu, s, t);
                float a2 = g_al2s[sj] + aldn;
                float e2 = a2 > 0.f ? a2 : NEG_SLOPE * a2;
                float w2 = __expf(e2);
                float2 h2 = *reinterpret_cast<const float2*>(&g_h2[(size_t)sj * HID + c0]);
                ax += w2 * h2.x; ay += w2 * h2.y; den += w2;
            }
        } else {
            for (int t = 0; t < rem; ++t) {
                int sj = __shfl_sync(0xffffffffu, s, t);
                float a2 = g_al2s[sj] + aldn;
                float e2 = a2 > 0.f ? a2 : NEG_SLOPE * a2;
                float w2 = __expf(e2);
                float2 h2 = *reinterpret_cast<const float2*>(&g_h2[(size_t)sj * HID + c0]);
                ax += w2 * h2.x; ay += w2 * h2.y; den += w2;
            }
        }
    }
    float inv = 1.f / (den + 1e-16f);
    float vx = ax * inv + s_b2[c0];
    float vy = ay * inv + s_b2[c0 + 1];
    vx = vx > 0.f ? vx : expm1f(vx);
    vy = vy > 0.f ? vy : expm1f(vy);
    int b = batch[n];
    red_add_v2(&g_pool[b * HID + c0], vx, vy);
    if (lane == 0) red_add_f(&g_cnt[b], 1.f);
}

// ---------------- K8: classifier + log_softmax ----------------
__global__ void k_cls(const float* __restrict__ Wc, const float* __restrict__ bc,
                      float* __restrict__ out) {
    __shared__ float Ws[HID * NCLS];
    __shared__ float bs[NCLS];
    for (int i = threadIdx.x; i < HID * NCLS; i += blockDim.x) Ws[i] = Wc[i];
    if (threadIdx.x < NCLS) bs[threadIdx.x] = bc[threadIdx.x];
    __syncthreads();
    int g = threadIdx.x;
    if (g >= NG) return;
    float inv = 1.f / fmaxf(g_cnt[g], 1.f);
    float logit[NCLS];
#pragma unroll
    for (int q = 0; q < NCLS; ++q) logit[q] = bs[q];
    for (int c = 0; c < HID; ++c) {
        float pv = g_pool[g * HID + c] * inv;
#pragma unroll
        for (int q = 0; q < NCLS; ++q) logit[q] += pv * Ws[c * NCLS + q];
    }
    float m = logit[0];
#pragma unroll
    for (int q = 1; q < NCLS; ++q) m = fmaxf(m, logit[q]);
    float ssum = 0.f;
#pragma unroll
    for (int q = 0; q < NCLS; ++q) ssum += expf(logit[q] - m);
    float lse = m + logf(ssum);
#pragma unroll
    for (int q = 0; q < NCLS; ++q) out[g * NCLS + q] = logit[q] - lse;
}

// ---------------- launcher ----------------
extern "C" void kernel_launch(void* const* d_in, const int* in_sizes, int n_in,
                              void* d_out, int out_size) {
    const float* x      = (const float*)d_in[0];
    const int*   ei     = (const int*)  d_in[1];
    const int*   batch  = (const int*)  d_in[2];
    const float* W1     = (const float*)d_in[3];
    const float* a_src1 = (const float*)d_in[4];
    const float* a_dst1 = (const float*)d_in[5];
    const float* b1     = (const float*)d_in[6];
    const float* W2     = (const float*)d_in[7];
    const float* a_src2 = (const float*)d_in[8];
    const float* a_dst2 = (const float*)d_in[9];
    const float* b2     = (const float*)d_in[10];
    const float* Wc     = (const float*)d_in[11];
    const float* bc     = (const float*)d_in[12];
    float* out = (float*)d_out;
    const int* srcp = ei;
    const int* dstp = ei + N_EDGES;

    static cudaStream_t s_side = nullptr;
    static cudaEvent_t  s_fork = nullptr, s_join = nullptr;
    if (s_side == nullptr) {
        cudaStreamCreateWithFlags(&s_side, cudaStreamNonBlocking);
        cudaEventCreateWithFlags(&s_fork, cudaEventDisableTiming);
        cudaEventCreateWithFlags(&s_join, cudaEventDisableTiming);
    }

    // fork: CSR build on side stream, GEMM path on main stream (independent dataflows)
    cudaEventRecord(s_fork, 0);
    cudaStreamWaitEvent(s_side, s_fork, 0);

    k_zs<<<(N_NODES + 255) / 256, 256, 0, s_side>>>();
    k_hist<<<(N_EDGES + 255) / 256, 256, 0, s_side>>>(dstp);
    k_scan<<<1, 1024, 0, s_side>>>();
    k_scatter<<<(N_EDGES + 255) / 256, 256, 0, s_side>>>(srcp, dstp);
    cudaEventRecord(s_join, s_side);

    k_prepW<<<(HID * KPAD + 255) / 256, 256>>>(W1);
    k_gemm1_mma<<<(N_NODES + 127) / 128, 256>>>(x, a_src1, a_dst1);

    // join: edge pass needs both GEMM output and CSR
    cudaStreamWaitEvent(0, s_join, 0);

    k_edge1_fused<<<1480, 256>>>(b1, W2, a_src2, a_dst2);
    k_edge2_csr<<<(N_NODES + 7) / 8, 256>>>(b2, batch);
    k_cls<<<1, 128>>>(Wc, bc, out);
}